// round 10
// baseline (speedup 1.0000x reference)
#include <cuda_runtime.h>
#include <cstdint>
#include <math.h>

// Problem dims (fixed by the reference)
#define BB 4
#define LL 1024
#define DD 1024
#define HH 16
#define HDD 64
#define MM (BB * LL)   // 4096

// Scratch in device globals (allocation is forbidden).
__device__ __align__(16) float g_q[BB * HH * LL * HDD];
__device__ __align__(16) float g_k[BB * HH * LL * HDD];
__device__ __align__(16) float g_v[BB * HH * LL * HDD];
__device__ __align__(16) float g_o[BB * HH * LL * HDD];

// ---- tf32 helpers (sm_80+ portable; compiles for base sm_103) ----
__device__ __forceinline__ float to_tf32(float x) {
    float y;
    asm("cvt.rna.tf32.f32 %0, %1;" : "=f"(y) : "f"(x));
    return y;
}
__device__ __forceinline__ void mma_tf32(float* d, const uint32_t* a, const uint32_t* b) {
    asm volatile(
        "mma.sync.aligned.m16n8k8.row.col.f32.tf32.tf32.f32 "
        "{%0,%1,%2,%3}, {%4,%5,%6,%7}, {%8,%9}, {%0,%1,%2,%3};"
        : "+f"(d[0]), "+f"(d[1]), "+f"(d[2]), "+f"(d[3])
        : "r"(a[0]), "r"(a[1]), "r"(a[2]), "r"(a[3]), "r"(b[0]), "r"(b[1]));
}

// Index helper: MODE 0 = row-major [M, D]; MODE 1 = [B, H, L, HD]
template <int MODE>
__device__ __forceinline__ int io_index(int m, int k) {
    if (MODE == 0) {
        return m * DD + k;
    } else {
        int b = m >> 10;
        int l = m & 1023;
        int h = k >> 6;
        int d = k & 63;
        return (((b * HH + h) * LL) + l) * HDD + d;
    }
}

// ---------------- tensor-core tf32 GEMM with register-prefetch pipeline ----------------
// C[M,N] = A[M,K] * W[N,K]^T + bias[N]   (torch Linear)
// CTA 128x128, BK=32, 8 warps (2 M x 4 N), warp tile 64x32 via m16n8k8.
// Pipeline: STS(c) -> sync -> LDG(c+1 into regs) -> MMA(c); LDG latency hides
// behind the 64-MMA burst instead of serializing with it.

#define BKC 32
#define SSTR 36   // smem row stride (floats)

template <int IN_MODE, int OUT_MODE>
__global__ __launch_bounds__(256, 2) void gemm_mma_kernel(
    const float* __restrict__ A0, const float* __restrict__ W0, const float* __restrict__ bias0, float* __restrict__ C0,
    const float* __restrict__ A1, const float* __restrict__ W1, const float* __restrict__ bias1, float* __restrict__ C1,
    const float* __restrict__ A2, const float* __restrict__ W2, const float* __restrict__ bias2, float* __restrict__ C2)
{
    const float* A = A0; const float* W = W0; const float* bias = bias0; float* C = C0;
    if (blockIdx.z == 1) { A = A1; W = W1; bias = bias1; C = C1; }
    else if (blockIdx.z == 2) { A = A2; W = W2; bias = bias2; C = C2; }

    __shared__ __align__(16) float As[128 * SSTR];   // [m][k']
    __shared__ __align__(16) float Bs[128 * SSTR];   // [n][k']

    const int tid = threadIdx.x;
    const int wid = tid >> 5;
    const int lane = tid & 31;
    const int g = lane >> 2;
    const int l = lane & 3;
    const int wm = wid & 1;
    const int wn = wid >> 1;

    const int m0 = blockIdx.y << 7;
    const int n0 = blockIdx.x << 7;

    const int srow[4] = { (tid + 0) >> 3, (tid + 256) >> 3, (tid + 512) >> 3, (tid + 768) >> 3 };
    const int scol = (tid & 7) << 2;

    float acc[4][4][4] = {};

    // Prologue: prefetch chunk 0 into registers.
    float4 ra[4], rb[4];
    #pragma unroll
    for (int p = 0; p < 4; ++p) {
        ra[p] = *(const float4*)(A + io_index<IN_MODE>(m0 + srow[p], scol));
        rb[p] = *(const float4*)(W + (n0 + srow[p]) * DD + scol);
    }

    for (int chunk = 0; chunk < DD / BKC; ++chunk) {
        __syncthreads();   // previous MMA readers done before overwrite
        #pragma unroll
        for (int p = 0; p < 4; ++p) {
            float4 av = ra[p], bv = rb[p];
            av.x = to_tf32(av.x); av.y = to_tf32(av.y); av.z = to_tf32(av.z); av.w = to_tf32(av.w);
            bv.x = to_tf32(bv.x); bv.y = to_tf32(bv.y); bv.z = to_tf32(bv.z); bv.w = to_tf32(bv.w);
            *(float4*)&As[srow[p] * SSTR + scol] = av;
            *(float4*)&Bs[srow[p] * SSTR + scol] = bv;
        }
        __syncthreads();

        // Prefetch next chunk (no dependence from the MMAs below).
        if (chunk + 1 < DD / BKC) {
            const int kn = (chunk + 1) * BKC;
            #pragma unroll
            for (int p = 0; p < 4; ++p) {
                ra[p] = *(const float4*)(A + io_index<IN_MODE>(m0 + srow[p], kn + scol));
                rb[p] = *(const float4*)(W + (n0 + srow[p]) * DD + (kn + scol));
            }
        }

        #pragma unroll
        for (int s = 0; s < 4; ++s) {
            const int ks = s << 3;

            uint32_t afr[4][4];
            #pragma unroll
            for (int mt = 0; mt < 4; ++mt) {
                const int rbse = wm * 64 + mt * 16;
                afr[mt][0] = __float_as_uint(As[(rbse + g) * SSTR + ks + l]);
                afr[mt][1] = __float_as_uint(As[(rbse + g + 8) * SSTR + ks + l]);
                afr[mt][2] = __float_as_uint(As[(rbse + g) * SSTR + ks + l + 4]);
                afr[mt][3] = __float_as_uint(As[(rbse + g + 8) * SSTR + ks + l + 4]);
            }
            uint32_t bfr[4][2];
            #pragma unroll
            for (int nt = 0; nt < 4; ++nt) {
                const int nb = wn * 32 + nt * 8;
                bfr[nt][0] = __float_as_uint(Bs[(nb + g) * SSTR + ks + l]);
                bfr[nt][1] = __float_as_uint(Bs[(nb + g) * SSTR + ks + l + 4]);
            }
            #pragma unroll
            for (int mt = 0; mt < 4; ++mt)
                #pragma unroll
                for (int nt = 0; nt < 4; ++nt)
                    mma_tf32(acc[mt][nt], afr[mt], bfr[nt]);
        }
    }

    #pragma unroll
    for (int nt = 0; nt < 4; ++nt) {
        const int n = n0 + wn * 32 + nt * 8 + 2 * l;
        const float b0 = bias[n];
        const float b1 = bias[n + 1];
        #pragma unroll
        for (int mt = 0; mt < 4; ++mt) {
            const int mlo = m0 + wm * 64 + mt * 16 + g;
            *(float2*)(C + io_index<OUT_MODE>(mlo, n)) =
                make_float2(acc[mt][nt][0] + b0, acc[mt][nt][1] + b1);
            *(float2*)(C + io_index<OUT_MODE>(mlo + 8, n)) =
                make_float2(acc[mt][nt][2] + b0, acc[mt][nt][3] + b1);
        }
    }
}

// ---------------- tensor-core tf32 flash attention (unchanged from R9 — passing) ----------------
#define ASTR 68
#define VSTR 72
#define ATT_SMEM ((128 * ASTR + 64 * ASTR + 64 * VSTR + 128 * ASTR) * 4)  // 105472 B

__global__ __launch_bounds__(256) void attn_mma_kernel()
{
    extern __shared__ __align__(16) float sm[];
    float* Qs = sm;                       // [128][ASTR] q-rows, tf32, pre-scaled
    float* Ks = Qs + 128 * ASTR;          // [64][ASTR]  key-rows, tf32
    float* Vs = Ks + 64 * ASTR;           // [64][VSTR]  key-rows, tf32
    float* Ps = Vs + 64 * VSTR;           // [128][ASTR] P staging (warp-private rows)

    const int bh = blockIdx.y;
    const int qt = blockIdx.x;
    const int q0 = qt << 7;

    const float* __restrict__ Qg = g_q + bh * (LL * HDD);
    const float* __restrict__ Kg = g_k + bh * (LL * HDD);
    const float* __restrict__ Vg = g_v + bh * (LL * HDD);

    const int tid = threadIdx.x;
    const int wid = tid >> 5;
    const int lane = tid & 31;
    const int g = lane >> 2;
    const int l = lane & 3;
    const int wrow = q0 + 16 * wid;

    #pragma unroll
    for (int p = 0; p < 8; ++p) {
        const int idx = tid + 256 * p;
        const int r = idx >> 4;
        const int c4 = (idx & 15) << 2;
        float4 qv = *(const float4*)&Qg[(q0 + r) * HDD + c4];
        qv.x = to_tf32(qv.x * 0.125f); qv.y = to_tf32(qv.y * 0.125f);
        qv.z = to_tf32(qv.z * 0.125f); qv.w = to_tf32(qv.w * 0.125f);
        *(float4*)&Qs[r * ASTR + c4] = qv;
    }

    float acc_o[8][4] = {};
    float m0 = -1e30f, m1 = -1e30f;
    float l0 = 0.0f, l1 = 0.0f;

    const int nkt = 2 * qt + 2;
    for (int kt = 0; kt < nkt; ++kt) {
        const int k0 = kt << 6;

        __syncthreads();
        #pragma unroll
        for (int p = 0; p < 4; ++p) {
            const int idx = tid + 256 * p;
            const int r = idx >> 4;
            const int c4 = (idx & 15) << 2;
            float4 kv = *(const float4*)&Kg[(k0 + r) * HDD + c4];
            float4 vv = *(const float4*)&Vg[(k0 + r) * HDD + c4];
            kv.x = to_tf32(kv.x); kv.y = to_tf32(kv.y); kv.z = to_tf32(kv.z); kv.w = to_tf32(kv.w);
            vv.x = to_tf32(vv.x); vv.y = to_tf32(vv.y); vv.z = to_tf32(vv.z); vv.w = to_tf32(vv.w);
            *(float4*)&Ks[r * ASTR + c4] = kv;
            *(float4*)&Vs[r * VSTR + c4] = vv;
        }
        __syncthreads();

        if (k0 > wrow + 15) continue;

        float s[8][4] = {};
        #pragma unroll
        for (int st = 0; st < 8; ++st) {
            const int ks = st << 3;
            uint32_t af[4];
            af[0] = __float_as_uint(Qs[(16 * wid + g) * ASTR + ks + l]);
            af[1] = __float_as_uint(Qs[(16 * wid + g + 8) * ASTR + ks + l]);
            af[2] = __float_as_uint(Qs[(16 * wid + g) * ASTR + ks + l + 4]);
            af[3] = __float_as_uint(Qs[(16 * wid + g + 8) * ASTR + ks + l + 4]);
            #pragma unroll
            for (int nt = 0; nt < 8; ++nt) {
                uint32_t bf[2];
                bf[0] = __float_as_uint(Ks[(nt * 8 + g) * ASTR + ks + l]);
                bf[1] = __float_as_uint(Ks[(nt * 8 + g) * ASTR + ks + l + 4]);
                mma_tf32(s[nt], af, bf);
            }
        }

        const int r0 = wrow + g;
        const int r1 = wrow + 8 + g;
        if (k0 + 63 > wrow) {
            #pragma unroll
            for (int nt = 0; nt < 8; ++nt) {
                const int c = k0 + nt * 8 + 2 * l;
                if (c > r0)     s[nt][0] = -1e30f;
                if (c + 1 > r0) s[nt][1] = -1e30f;
                if (c > r1)     s[nt][2] = -1e30f;
                if (c + 1 > r1) s[nt][3] = -1e30f;
            }
        }

        float mx0 = -1e30f, mx1 = -1e30f;
        #pragma unroll
        for (int nt = 0; nt < 8; ++nt) {
            mx0 = fmaxf(mx0, fmaxf(s[nt][0], s[nt][1]));
            mx1 = fmaxf(mx1, fmaxf(s[nt][2], s[nt][3]));
        }
        #pragma unroll
        for (int off = 2; off >= 1; off >>= 1) {
            mx0 = fmaxf(mx0, __shfl_xor_sync(0xffffffffu, mx0, off));
            mx1 = fmaxf(mx1, __shfl_xor_sync(0xffffffffu, mx1, off));
        }
        const float mn0 = fmaxf(m0, mx0);
        const float mn1 = fmaxf(m1, mx1);
        const float a0 = __expf(m0 - mn0);
        const float a1 = __expf(m1 - mn1);

        float sum0 = 0.0f, sum1 = 0.0f;
        #pragma unroll
        for (int nt = 0; nt < 8; ++nt) {
            s[nt][0] = __expf(s[nt][0] - mn0); sum0 += s[nt][0];
            s[nt][1] = __expf(s[nt][1] - mn0); sum0 += s[nt][1];
            s[nt][2] = __expf(s[nt][2] - mn1); sum1 += s[nt][2];
            s[nt][3] = __expf(s[nt][3] - mn1); sum1 += s[nt][3];
        }
        #pragma unroll
        for (int off = 2; off >= 1; off >>= 1) {
            sum0 += __shfl_xor_sync(0xffffffffu, sum0, off);
            sum1 += __shfl_xor_sync(0xffffffffu, sum1, off);
        }
        l0 = l0 * a0 + sum0;
        l1 = l1 * a1 + sum1;
        m0 = mn0;
        m1 = mn1;

        #pragma unroll
        for (int nt = 0; nt < 8; ++nt) {
            acc_o[nt][0] *= a0; acc_o[nt][1] *= a0;
            acc_o[nt][2] *= a1; acc_o[nt][3] *= a1;
        }

        #pragma unroll
        for (int nt = 0; nt < 8; ++nt) {
            *(float2*)&Ps[(16 * wid + g) * ASTR + nt * 8 + 2 * l] =
                make_float2(to_tf32(s[nt][0]), to_tf32(s[nt][1]));
            *(float2*)&Ps[(16 * wid + g + 8) * ASTR + nt * 8 + 2 * l] =
                make_float2(to_tf32(s[nt][2]), to_tf32(s[nt][3]));
        }
        __syncwarp();

        #pragma unroll
        for (int st = 0; st < 8; ++st) {
            const int ks = st << 3;
            uint32_t af[4];
            af[0] = __float_as_uint(Ps[(16 * wid + g) * ASTR + ks + l]);
            af[1] = __float_as_uint(Ps[(16 * wid + g + 8) * ASTR + ks + l]);
            af[2] = __float_as_uint(Ps[(16 * wid + g) * ASTR + ks + l + 4]);
            af[3] = __float_as_uint(Ps[(16 * wid + g + 8) * ASTR + ks + l + 4]);
            #pragma unroll
            for (int nt = 0; nt < 8; ++nt) {
                uint32_t bf[2];
                bf[0] = __float_as_uint(Vs[(ks + l) * VSTR + nt * 8 + g]);
                bf[1] = __float_as_uint(Vs[(ks + l + 4) * VSTR + nt * 8 + g]);
                mma_tf32(acc_o[nt], af, bf);
            }
        }
    }

    float* Og = g_o + bh * (LL * HDD);
    const float inv0 = 1.0f / l0;
    const float inv1 = 1.0f / l1;
    const int r0 = wrow + g;
    const int r1 = wrow + 8 + g;
    #pragma unroll
    for (int nt = 0; nt < 8; ++nt) {
        const int d = nt * 8 + 2 * l;
        *(float2*)&Og[r0 * HDD + d] = make_float2(acc_o[nt][0] * inv0, acc_o[nt][1] * inv0);
        *(float2*)&Og[r1 * HDD + d] = make_float2(acc_o[nt][2] * inv1, acc_o[nt][3] * inv1);
    }
}

extern "C" void kernel_launch(void* const* d_in, const int* in_sizes, int n_in,
                              void* d_out, int out_size)
{
    (void)in_sizes; (void)n_in; (void)out_size;

    const float* key   = (const float*)d_in[0];
    const float* value = (const float*)d_in[1];
    const float* query = (const float*)d_in[2];
    const float* Wk    = (const float*)d_in[3];
    const float* bk    = (const float*)d_in[4];
    const float* Wq    = (const float*)d_in[5];
    const float* bq    = (const float*)d_in[6];
    const float* Wv    = (const float*)d_in[7];
    const float* bv    = (const float*)d_in[8];
    const float* Wp    = (const float*)d_in[9];
    const float* bp    = (const float*)d_in[10];
    float* out = (float*)d_out;

    float *q_p, *k_p, *v_p, *o_p;
    cudaGetSymbolAddress((void**)&q_p, g_q);
    cudaGetSymbolAddress((void**)&k_p, g_k);
    cudaGetSymbolAddress((void**)&v_p, g_v);
    cudaGetSymbolAddress((void**)&o_p, g_o);

    // Fused Q/K/V projections -> [B,H,L,HD]  (tensor-core tf32, prefetch pipeline)
    gemm_mma_kernel<0, 1><<<dim3(DD / 128, MM / 128, 3), 256>>>(
        query, Wq, bq, q_p,
        key,   Wk, bk, k_p,
        value, Wv, bv, v_p);

    // Attention (tensor-core tf32 flash)
    cudaFuncSetAttribute(attn_mma_kernel, cudaFuncAttributeMaxDynamicSharedMemorySize, ATT_SMEM);
    attn_mma_kernel<<<dim3(LL / 128, BB * HH), 256, ATT_SMEM>>>();

    // Output projection: gather [B,H,L,HD] -> [B,L,D]  (tensor-core tf32, prefetch pipeline)
    gemm_mma_kernel<1, 0><<<dim3(DD / 128, MM / 128, 1), 256>>>(
        o_p, Wp, bp, out,
        o_p, Wp, bp, out,
        o_p, Wp, bp, out);
}

// round 11
// speedup vs baseline: 1.1472x; 1.1472x over previous
#include <cuda_runtime.h>
#include <cstdint>
#include <math.h>

// Problem dims (fixed by the reference)
#define BB 4
#define LL 1024
#define DD 1024
#define HH 16
#define HDD 64
#define MM (BB * LL)   // 4096

// Scratch in device globals (allocation is forbidden).
__device__ __align__(16) float g_q[BB * HH * LL * HDD];
__device__ __align__(16) float g_k[BB * HH * LL * HDD];
__device__ __align__(16) float g_v[BB * HH * LL * HDD];
__device__ __align__(16) float g_o[BB * HH * LL * HDD];
// tf32-rounded operand copies
__device__ __align__(16) float g_aq[MM * DD];
__device__ __align__(16) float g_ak[MM * DD];
__device__ __align__(16) float g_av[MM * DD];
__device__ __align__(16) float g_wq[DD * DD];
__device__ __align__(16) float g_wk[DD * DD];
__device__ __align__(16) float g_wv[DD * DD];
__device__ __align__(16) float g_wp[DD * DD];

// ---- tf32 helpers (sm_80+ portable; compiles for base sm_103) ----
__device__ __forceinline__ float to_tf32(float x) {
    float y;
    asm("cvt.rna.tf32.f32 %0, %1;" : "=f"(y) : "f"(x));
    return y;
}
__device__ __forceinline__ void mma_tf32(float* d, const uint32_t* a, const uint32_t* b) {
    asm volatile(
        "mma.sync.aligned.m16n8k8.row.col.f32.tf32.tf32.f32 "
        "{%0,%1,%2,%3}, {%4,%5,%6,%7}, {%8,%9}, {%0,%1,%2,%3};"
        : "+f"(d[0]), "+f"(d[1]), "+f"(d[2]), "+f"(d[3])
        : "r"(a[0]), "r"(a[1]), "r"(a[2]), "r"(a[3]), "r"(b[0]), "r"(b[1]));
}
__device__ __forceinline__ uint32_t smem_u32(const void* p) {
    uint32_t a;
    asm("{ .reg .u64 t; cvta.to.shared.u64 t, %1; cvt.u32.u64 %0, t; }" : "=r"(a) : "l"(p));
    return a;
}
__device__ __forceinline__ void cp16(uint32_t dst_smem, const void* src) {
    asm volatile("cp.async.cg.shared.global [%0], [%1], 16;" :: "r"(dst_smem), "l"(src));
}
#define CP_COMMIT() asm volatile("cp.async.commit_group;" ::: "memory")
#define CP_WAIT1()  asm volatile("cp.async.wait_group 1;" ::: "memory")
#define CP_WAIT0()  asm volatile("cp.async.wait_group 0;" ::: "memory")

// Index helper: MODE 0 = row-major [M, D]; MODE 1 = [B, H, L, HD]
template <int MODE>
__device__ __forceinline__ int io_index(int m, int k) {
    if (MODE == 0) {
        return m * DD + k;
    } else {
        int b = m >> 10;
        int l = m & 1023;
        int h = k >> 6;
        int d = k & 63;
        return (((b * HH + h) * LL) + l) * HDD + d;
    }
}

// ---------------- prepass: round operands to tf32 once ----------------
__global__ __launch_bounds__(256) void tf32_prepass_kernel(
    const float* __restrict__ s0, float* __restrict__ d0, int n0_,
    const float* __restrict__ s1, float* __restrict__ d1, int n1_,
    const float* __restrict__ s2, float* __restrict__ d2, int n2_,
    const float* __restrict__ s3, float* __restrict__ d3, int n3_,
    const float* __restrict__ s4, float* __restrict__ d4, int n4_,
    const float* __restrict__ s5, float* __restrict__ d5, int n5_,
    const float* __restrict__ s6, float* __restrict__ d6, int n6_)
{
    const float* src; float* dst; int n;
    switch (blockIdx.z) {
        case 0: src = s0; dst = d0; n = n0_; break;
        case 1: src = s1; dst = d1; n = n1_; break;
        case 2: src = s2; dst = d2; n = n2_; break;
        case 3: src = s3; dst = d3; n = n3_; break;
        case 4: src = s4; dst = d4; n = n4_; break;
        case 5: src = s5; dst = d5; n = n5_; break;
        default: src = s6; dst = d6; n = n6_; break;
    }
    const int nf4 = n >> 2;
    for (int i = blockIdx.x * blockDim.x + threadIdx.x; i < nf4; i += gridDim.x * blockDim.x) {
        float4 v = ((const float4*)src)[i];
        v.x = to_tf32(v.x); v.y = to_tf32(v.y); v.z = to_tf32(v.z); v.w = to_tf32(v.w);
        ((float4*)dst)[i] = v;
    }
}

// ---------------- tensor-core tf32 GEMM, cp.async 3-stage pipeline ----------------
// C[M,N] = A[M,K] * W[N,K]^T + bias[N]; operands PRE-ROUNDED to tf32.
// CTA 128x128, BK=32, 8 warps (2 M x 4 N), warp tile 64x32 via m16n8k8.

#define BKC 32
#define SSTR 36                         // smem row stride (floats)
#define STAGE_F (2 * 128 * SSTR)        // floats per stage (A+B)
#define NCH (DD / BKC)                  // 32
#define GSMEM (3 * STAGE_F * 4)         // 110592 B

template <int IN_MODE, int OUT_MODE>
__global__ __launch_bounds__(256, 2) void gemm_mma_kernel(
    const float* __restrict__ A0, const float* __restrict__ W0, const float* __restrict__ bias0, float* __restrict__ C0,
    const float* __restrict__ A1, const float* __restrict__ W1, const float* __restrict__ bias1, float* __restrict__ C1,
    const float* __restrict__ A2, const float* __restrict__ W2, const float* __restrict__ bias2, float* __restrict__ C2)
{
    const float* A = A0; const float* W = W0; const float* bias = bias0; float* C = C0;
    if (blockIdx.z == 1) { A = A1; W = W1; bias = bias1; C = C1; }
    else if (blockIdx.z == 2) { A = A2; W = W2; bias = bias2; C = C2; }

    extern __shared__ __align__(16) float smem[];

    const int tid = threadIdx.x;
    const int wid = tid >> 5;
    const int lane = tid & 31;
    const int g = lane >> 2;
    const int l = lane & 3;
    const int wm = wid & 1;
    const int wn = wid >> 1;

    const int m0 = blockIdx.y << 7;
    const int n0 = blockIdx.x << 7;

    const int srow[4] = { (tid + 0) >> 3, (tid + 256) >> 3, (tid + 512) >> 3, (tid + 768) >> 3 };
    const int scol = (tid & 7) << 2;

    // Per-thread smem write offsets (bytes) within a stage, for the 8 cp.asyncs.
    uint32_t sa[4], sb[4];
    #pragma unroll
    for (int p = 0; p < 4; ++p) {
        sa[p] = smem_u32(&smem[srow[p] * SSTR + scol]);
        sb[p] = smem_u32(&smem[128 * SSTR + srow[p] * SSTR + scol]);
    }

    float acc[4][4][4] = {};

    // Prologue: stage 0 <- chunk 0
    #pragma unroll
    for (int p = 0; p < 4; ++p) {
        cp16(sa[p], A + io_index<IN_MODE>(m0 + srow[p], scol));
        cp16(sb[p], W + (n0 + srow[p]) * DD + scol);
    }
    CP_COMMIT();

    for (int chunk = 0; chunk < NCH; ++chunk) {
        const int cur = chunk % 3;
        if (chunk + 1 < NCH) {
            const int nxt = (chunk + 1) % 3;
            const int kn = (chunk + 1) * BKC;
            const uint32_t soff = (uint32_t)(nxt * STAGE_F * 4);
            #pragma unroll
            for (int p = 0; p < 4; ++p) {
                cp16(sa[p] + soff, A + io_index<IN_MODE>(m0 + srow[p], kn + scol));
                cp16(sb[p] + soff, W + (n0 + srow[p]) * DD + (kn + scol));
            }
            CP_COMMIT();
            CP_WAIT1();
        } else {
            CP_WAIT0();
        }
        __syncthreads();

        const float* As = smem + cur * STAGE_F;
        const float* Bs = As + 128 * SSTR;

        #pragma unroll
        for (int s = 0; s < 4; ++s) {
            const int ks = s << 3;

            uint32_t afr[4][4];
            #pragma unroll
            for (int mt = 0; mt < 4; ++mt) {
                const int rbse = wm * 64 + mt * 16;
                afr[mt][0] = __float_as_uint(As[(rbse + g) * SSTR + ks + l]);
                afr[mt][1] = __float_as_uint(As[(rbse + g + 8) * SSTR + ks + l]);
                afr[mt][2] = __float_as_uint(As[(rbse + g) * SSTR + ks + l + 4]);
                afr[mt][3] = __float_as_uint(As[(rbse + g + 8) * SSTR + ks + l + 4]);
            }
            uint32_t bfr[4][2];
            #pragma unroll
            for (int nt = 0; nt < 4; ++nt) {
                const int nb = wn * 32 + nt * 8;
                bfr[nt][0] = __float_as_uint(Bs[(nb + g) * SSTR + ks + l]);
                bfr[nt][1] = __float_as_uint(Bs[(nb + g) * SSTR + ks + l + 4]);
            }
            #pragma unroll
            for (int mt = 0; mt < 4; ++mt)
                #pragma unroll
                for (int nt = 0; nt < 4; ++nt)
                    mma_tf32(acc[mt][nt], afr[mt], bfr[nt]);
        }
    }

    #pragma unroll
    for (int nt = 0; nt < 4; ++nt) {
        const int n = n0 + wn * 32 + nt * 8 + 2 * l;
        const float b0 = bias[n];
        const float b1 = bias[n + 1];
        #pragma unroll
        for (int mt = 0; mt < 4; ++mt) {
            const int mlo = m0 + wm * 64 + mt * 16 + g;
            *(float2*)(C + io_index<OUT_MODE>(mlo, n)) =
                make_float2(acc[mt][nt][0] + b0, acc[mt][nt][1] + b1);
            *(float2*)(C + io_index<OUT_MODE>(mlo + 8, n)) =
                make_float2(acc[mt][nt][2] + b0, acc[mt][nt][3] + b1);
        }
    }
}

// ---------------- tensor-core tf32 flash attention (R9; O written tf32-rounded) ----------------
#define ASTR 68
#define VSTR 72
#define ATT_SMEM ((128 * ASTR + 64 * ASTR + 64 * VSTR + 128 * ASTR) * 4)  // 105472 B

__global__ __launch_bounds__(256) void attn_mma_kernel()
{
    extern __shared__ __align__(16) float sm[];
    float* Qs = sm;                       // [128][ASTR]
    float* Ks = Qs + 128 * ASTR;          // [64][ASTR]
    float* Vs = Ks + 64 * ASTR;           // [64][VSTR]
    float* Ps = Vs + 64 * VSTR;           // [128][ASTR]

    const int bh = blockIdx.y;
    const int qt = blockIdx.x;
    const int q0 = qt << 7;

    const float* __restrict__ Qg = g_q + bh * (LL * HDD);
    const float* __restrict__ Kg = g_k + bh * (LL * HDD);
    const float* __restrict__ Vg = g_v + bh * (LL * HDD);

    const int tid = threadIdx.x;
    const int wid = tid >> 5;
    const int lane = tid & 31;
    const int g = lane >> 2;
    const int l = lane & 3;
    const int wrow = q0 + 16 * wid;

    #pragma unroll
    for (int p = 0; p < 8; ++p) {
        const int idx = tid + 256 * p;
        const int r = idx >> 4;
        const int c4 = (idx & 15) << 2;
        float4 qv = *(const float4*)&Qg[(q0 + r) * HDD + c4];
        qv.x = to_tf32(qv.x * 0.125f); qv.y = to_tf32(qv.y * 0.125f);
        qv.z = to_tf32(qv.z * 0.125f); qv.w = to_tf32(qv.w * 0.125f);
        *(float4*)&Qs[r * ASTR + c4] = qv;
    }

    float acc_o[8][4] = {};
    float m0 = -1e30f, m1 = -1e30f;
    float l0 = 0.0f, l1 = 0.0f;

    const int nkt = 2 * qt + 2;
    for (int kt = 0; kt < nkt; ++kt) {
        const int k0 = kt << 6;

        __syncthreads();
        #pragma unroll
        for (int p = 0; p < 4; ++p) {
            const int idx = tid + 256 * p;
            const int r = idx >> 4;
            const int c4 = (idx & 15) << 2;
            float4 kv = *(const float4*)&Kg[(k0 + r) * HDD + c4];
            float4 vv = *(const float4*)&Vg[(k0 + r) * HDD + c4];
            kv.x = to_tf32(kv.x); kv.y = to_tf32(kv.y); kv.z = to_tf32(kv.z); kv.w = to_tf32(kv.w);
            vv.x = to_tf32(vv.x); vv.y = to_tf32(vv.y); vv.z = to_tf32(vv.z); vv.w = to_tf32(vv.w);
            *(float4*)&Ks[r * ASTR + c4] = kv;
            *(float4*)&Vs[r * VSTR + c4] = vv;
        }
        __syncthreads();

        if (k0 > wrow + 15) continue;

        float s[8][4] = {};
        #pragma unroll
        for (int st = 0; st < 8; ++st) {
            const int ks = st << 3;
            uint32_t af[4];
            af[0] = __float_as_uint(Qs[(16 * wid + g) * ASTR + ks + l]);
            af[1] = __float_as_uint(Qs[(16 * wid + g + 8) * ASTR + ks + l]);
            af[2] = __float_as_uint(Qs[(16 * wid + g) * ASTR + ks + l + 4]);
            af[3] = __float_as_uint(Qs[(16 * wid + g + 8) * ASTR + ks + l + 4]);
            #pragma unroll
            for (int nt = 0; nt < 8; ++nt) {
                uint32_t bf[2];
                bf[0] = __float_as_uint(Ks[(nt * 8 + g) * ASTR + ks + l]);
                bf[1] = __float_as_uint(Ks[(nt * 8 + g) * ASTR + ks + l + 4]);
                mma_tf32(s[nt], af, bf);
            }
        }

        const int r0 = wrow + g;
        const int r1 = wrow + 8 + g;
        if (k0 + 63 > wrow) {
            #pragma unroll
            for (int nt = 0; nt < 8; ++nt) {
                const int c = k0 + nt * 8 + 2 * l;
                if (c > r0)     s[nt][0] = -1e30f;
                if (c + 1 > r0) s[nt][1] = -1e30f;
                if (c > r1)     s[nt][2] = -1e30f;
                if (c + 1 > r1) s[nt][3] = -1e30f;
            }
        }

        float mx0 = -1e30f, mx1 = -1e30f;
        #pragma unroll
        for (int nt = 0; nt < 8; ++nt) {
            mx0 = fmaxf(mx0, fmaxf(s[nt][0], s[nt][1]));
            mx1 = fmaxf(mx1, fmaxf(s[nt][2], s[nt][3]));
        }
        #pragma unroll
        for (int off = 2; off >= 1; off >>= 1) {
            mx0 = fmaxf(mx0, __shfl_xor_sync(0xffffffffu, mx0, off));
            mx1 = fmaxf(mx1, __shfl_xor_sync(0xffffffffu, mx1, off));
        }
        const float mn0 = fmaxf(m0, mx0);
        const float mn1 = fmaxf(m1, mx1);
        const float a0 = __expf(m0 - mn0);
        const float a1 = __expf(m1 - mn1);

        float sum0 = 0.0f, sum1 = 0.0f;
        #pragma unroll
        for (int nt = 0; nt < 8; ++nt) {
            s[nt][0] = __expf(s[nt][0] - mn0); sum0 += s[nt][0];
            s[nt][1] = __expf(s[nt][1] - mn0); sum0 += s[nt][1];
            s[nt][2] = __expf(s[nt][2] - mn1); sum1 += s[nt][2];
            s[nt][3] = __expf(s[nt][3] - mn1); sum1 += s[nt][3];
        }
        #pragma unroll
        for (int off = 2; off >= 1; off >>= 1) {
            sum0 += __shfl_xor_sync(0xffffffffu, sum0, off);
            sum1 += __shfl_xor_sync(0xffffffffu, sum1, off);
        }
        l0 = l0 * a0 + sum0;
        l1 = l1 * a1 + sum1;
        m0 = mn0;
        m1 = mn1;

        #pragma unroll
        for (int nt = 0; nt < 8; ++nt) {
            acc_o[nt][0] *= a0; acc_o[nt][1] *= a0;
            acc_o[nt][2] *= a1; acc_o[nt][3] *= a1;
        }

        #pragma unroll
        for (int nt = 0; nt < 8; ++nt) {
            *(float2*)&Ps[(16 * wid + g) * ASTR + nt * 8 + 2 * l] =
                make_float2(to_tf32(s[nt][0]), to_tf32(s[nt][1]));
            *(float2*)&Ps[(16 * wid + g + 8) * ASTR + nt * 8 + 2 * l] =
                make_float2(to_tf32(s[nt][2]), to_tf32(s[nt][3]));
        }
        __syncwarp();

        #pragma unroll
        for (int st = 0; st < 8; ++st) {
            const int ks = st << 3;
            uint32_t af[4];
            af[0] = __float_as_uint(Ps[(16 * wid + g) * ASTR + ks + l]);
            af[1] = __float_as_uint(Ps[(16 * wid + g + 8) * ASTR + ks + l]);
            af[2] = __float_as_uint(Ps[(16 * wid + g) * ASTR + ks + l + 4]);
            af[3] = __float_as_uint(Ps[(16 * wid + g + 8) * ASTR + ks + l + 4]);
            #pragma unroll
            for (int nt = 0; nt < 8; ++nt) {
                uint32_t bf[2];
                bf[0] = __float_as_uint(Vs[(ks + l) * VSTR + nt * 8 + g]);
                bf[1] = __float_as_uint(Vs[(ks + l + 4) * VSTR + nt * 8 + g]);
                mma_tf32(acc_o[nt], af, bf);
            }
        }
    }

    // Normalize and write O rows, tf32-rounded (feeds the O-projection GEMM raw).
    float* Og = g_o + bh * (LL * HDD);
    const float inv0 = 1.0f / l0;
    const float inv1 = 1.0f / l1;
    const int r0 = wrow + g;
    const int r1 = wrow + 8 + g;
    #pragma unroll
    for (int nt = 0; nt < 8; ++nt) {
        const int d = nt * 8 + 2 * l;
        *(float2*)&Og[r0 * HDD + d] =
            make_float2(to_tf32(acc_o[nt][0] * inv0), to_tf32(acc_o[nt][1] * inv0));
        *(float2*)&Og[r1 * HDD + d] =
            make_float2(to_tf32(acc_o[nt][2] * inv1), to_tf32(acc_o[nt][3] * inv1));
    }
}

extern "C" void kernel_launch(void* const* d_in, const int* in_sizes, int n_in,
                              void* d_out, int out_size)
{
    (void)in_sizes; (void)n_in; (void)out_size;

    const float* key   = (const float*)d_in[0];
    const float* value = (const float*)d_in[1];
    const float* query = (const float*)d_in[2];
    const float* Wk    = (const float*)d_in[3];
    const float* bk    = (const float*)d_in[4];
    const float* Wq    = (const float*)d_in[5];
    const float* bq    = (const float*)d_in[6];
    const float* Wv    = (const float*)d_in[7];
    const float* bv    = (const float*)d_in[8];
    const float* Wp    = (const float*)d_in[9];
    const float* bp    = (const float*)d_in[10];
    float* out = (float*)d_out;

    float *q_p, *k_p, *v_p, *o_p;
    float *aq_p, *ak_p, *av_p, *wq_p, *wk_p, *wv_p, *wp_p;
    cudaGetSymbolAddress((void**)&q_p, g_q);
    cudaGetSymbolAddress((void**)&k_p, g_k);
    cudaGetSymbolAddress((void**)&v_p, g_v);
    cudaGetSymbolAddress((void**)&o_p, g_o);
    cudaGetSymbolAddress((void**)&aq_p, g_aq);
    cudaGetSymbolAddress((void**)&ak_p, g_ak);
    cudaGetSymbolAddress((void**)&av_p, g_av);
    cudaGetSymbolAddress((void**)&wq_p, g_wq);
    cudaGetSymbolAddress((void**)&wk_p, g_wk);
    cudaGetSymbolAddress((void**)&wv_p, g_wv);
    cudaGetSymbolAddress((void**)&wp_p, g_wp);

    // Prepass: round all GEMM operands to tf32 once.
    tf32_prepass_kernel<<<dim3(512, 1, 7), 256>>>(
        query, aq_p, MM * DD,
        key,   ak_p, MM * DD,
        value, av_p, MM * DD,
        Wq,    wq_p, DD * DD,
        Wk,    wk_p, DD * DD,
        Wv,    wv_p, DD * DD,
        Wp,    wp_p, DD * DD);

    cudaFuncSetAttribute(gemm_mma_kernel<0, 1>, cudaFuncAttributeMaxDynamicSharedMemorySize, GSMEM);
    cudaFuncSetAttribute(gemm_mma_kernel<1, 0>, cudaFuncAttributeMaxDynamicSharedMemorySize, GSMEM);

    // Fused Q/K/V projections -> [B,H,L,HD]  (tf32 MMA, cp.async pipeline)
    gemm_mma_kernel<0, 1><<<dim3(DD / 128, MM / 128, 3), 256, GSMEM>>>(
        aq_p, wq_p, bq, q_p,
        ak_p, wk_p, bk, k_p,
        av_p, wv_p, bv, v_p);

    // Attention (tensor-core tf32 flash)
    cudaFuncSetAttribute(attn_mma_kernel, cudaFuncAttributeMaxDynamicSharedMemorySize, ATT_SMEM);
    attn_mma_kernel<<<dim3(LL / 128, BB * HH), 256, ATT_SMEM>>>();

    // Output projection: gather [B,H,L,HD] -> [B,L,D]
    gemm_mma_kernel<1, 0><<<dim3(DD / 128, MM / 128, 1), 256, GSMEM>>>(
        o_p, wp_p, bp, out,
        o_p, wp_p, bp, out,
        o_p, wp_p, bp, out);
}

// round 15
// speedup vs baseline: 1.1599x; 1.0110x over previous
#include <cuda_runtime.h>
#include <cstdint>
#include <math.h>

// Problem dims (fixed by the reference)
#define BB 4
#define LL 1024
#define DD 1024
#define HH 16
#define HDD 64
#define MM (BB * LL)   // 4096

// Scratch in device globals (allocation is forbidden).
__device__ __align__(16) float g_q[BB * HH * LL * HDD];
__device__ __align__(16) float g_k[BB * HH * LL * HDD];
__device__ __align__(16) float g_v[BB * HH * LL * HDD];
__device__ __align__(16) float g_o[BB * HH * LL * HDD];
// tf32-rounded operand copies
__device__ __align__(16) float g_aq[MM * DD];
__device__ __align__(16) float g_ak[MM * DD];
__device__ __align__(16) float g_av[MM * DD];
__device__ __align__(16) float g_wq[DD * DD];
__device__ __align__(16) float g_wk[DD * DD];
__device__ __align__(16) float g_wv[DD * DD];
__device__ __align__(16) float g_wp[DD * DD];

// ---- tf32 helpers (sm_80+ portable; compiles for base sm_103) ----
__device__ __forceinline__ float to_tf32(float x) {
    float y;
    asm("cvt.rna.tf32.f32 %0, %1;" : "=f"(y) : "f"(x));
    return y;
}
__device__ __forceinline__ void mma_tf32(float* d, const uint32_t* a, const uint32_t* b) {
    asm volatile(
        "mma.sync.aligned.m16n8k8.row.col.f32.tf32.tf32.f32 "
        "{%0,%1,%2,%3}, {%4,%5,%6,%7}, {%8,%9}, {%0,%1,%2,%3};"
        : "+f"(d[0]), "+f"(d[1]), "+f"(d[2]), "+f"(d[3])
        : "r"(a[0]), "r"(a[1]), "r"(a[2]), "r"(a[3]), "r"(b[0]), "r"(b[1]));
}
__device__ __forceinline__ uint32_t smem_u32(const void* p) {
    uint32_t a;
    asm("{ .reg .u64 t; cvta.to.shared.u64 t, %1; cvt.u32.u64 %0, t; }" : "=r"(a) : "l"(p));
    return a;
}
__device__ __forceinline__ void cp16(uint32_t dst_smem, const void* src) {
    asm volatile("cp.async.cg.shared.global [%0], [%1], 16;" :: "r"(dst_smem), "l"(src));
}
#define CP_COMMIT() asm volatile("cp.async.commit_group;" ::: "memory")
#define CP_WAIT1()  asm volatile("cp.async.wait_group 1;" ::: "memory")
#define CP_WAIT0()  asm volatile("cp.async.wait_group 0;" ::: "memory")

// Index helper: MODE 0 = row-major [M, D]; MODE 1 = [B, H, L, HD]
template <int MODE>
__device__ __forceinline__ int io_index(int m, int k) {
    if (MODE == 0) {
        return m * DD + k;
    } else {
        int b = m >> 10;
        int l = m & 1023;
        int h = k >> 6;
        int d = k & 63;
        return (((b * HH + h) * LL) + l) * HDD + d;
    }
}

// ---------------- prepass: round operands to tf32 once ----------------
__global__ __launch_bounds__(256) void tf32_prepass_kernel(
    const float* __restrict__ s0, float* __restrict__ d0, int n0_,
    const float* __restrict__ s1, float* __restrict__ d1, int n1_,
    const float* __restrict__ s2, float* __restrict__ d2, int n2_,
    const float* __restrict__ s3, float* __restrict__ d3, int n3_,
    const float* __restrict__ s4, float* __restrict__ d4, int n4_,
    const float* __restrict__ s5, float* __restrict__ d5, int n5_,
    const float* __restrict__ s6, float* __restrict__ d6, int n6_)
{
    const float* src; float* dst; int n;
    switch (blockIdx.z) {
        case 0: src = s0; dst = d0; n = n0_; break;
        case 1: src = s1; dst = d1; n = n1_; break;
        case 2: src = s2; dst = d2; n = n2_; break;
        case 3: src = s3; dst = d3; n = n3_; break;
        case 4: src = s4; dst = d4; n = n4_; break;
        case 5: src = s5; dst = d5; n = n5_; break;
        default: src = s6; dst = d6; n = n6_; break;
    }
    const int nf4 = n >> 2;
    for (int i = blockIdx.x * blockDim.x + threadIdx.x; i < nf4; i += gridDim.x * blockDim.x) {
        float4 v = ((const float4*)src)[i];
        v.x = to_tf32(v.x); v.y = to_tf32(v.y); v.z = to_tf32(v.z); v.w = to_tf32(v.w);
        ((float4*)dst)[i] = v;
    }
}

// ---------------- tensor-core tf32 GEMM, cp.async 3-stage pipeline ----------------
// C[M,N] = A[M,K] * W[N,K]^T + bias[N]; operands PRE-ROUNDED to tf32.
// OUT_MODE==1 (QKV outputs) additionally writes tf32-rounded results so the
// attention kernel can cp.async them without conversion.

#define BKC 32
#define SSTR 36                         // smem row stride (floats)
#define STAGE_F (2 * 128 * SSTR)        // floats per stage (A+B)
#define NCH (DD / BKC)                  // 32
#define GSMEM (3 * STAGE_F * 4)         // 110592 B

template <int IN_MODE, int OUT_MODE>
__global__ __launch_bounds__(256, 2) void gemm_mma_kernel(
    const float* __restrict__ A0, const float* __restrict__ W0, const float* __restrict__ bias0, float* __restrict__ C0,
    const float* __restrict__ A1, const float* __restrict__ W1, const float* __restrict__ bias1, float* __restrict__ C1,
    const float* __restrict__ A2, const float* __restrict__ W2, const float* __restrict__ bias2, float* __restrict__ C2)
{
    const float* A = A0; const float* W = W0; const float* bias = bias0; float* C = C0;
    if (blockIdx.z == 1) { A = A1; W = W1; bias = bias1; C = C1; }
    else if (blockIdx.z == 2) { A = A2; W = W2; bias = bias2; C = C2; }

    extern __shared__ __align__(16) float smem[];

    const int tid = threadIdx.x;
    const int wid = tid >> 5;
    const int lane = tid & 31;
    const int g = lane >> 2;
    const int l = lane & 3;
    const int wm = wid & 1;
    const int wn = wid >> 1;

    const int m0 = blockIdx.y << 7;
    const int n0 = blockIdx.x << 7;

    const int srow[4] = { (tid + 0) >> 3, (tid + 256) >> 3, (tid + 512) >> 3, (tid + 768) >> 3 };
    const int scol = (tid & 7) << 2;

    uint32_t sa[4], sb[4];
    #pragma unroll
    for (int p = 0; p < 4; ++p) {
        sa[p] = smem_u32(&smem[srow[p] * SSTR + scol]);
        sb[p] = smem_u32(&smem[128 * SSTR + srow[p] * SSTR + scol]);
    }

    float acc[4][4][4] = {};

    #pragma unroll
    for (int p = 0; p < 4; ++p) {
        cp16(sa[p], A + io_index<IN_MODE>(m0 + srow[p], scol));
        cp16(sb[p], W + (n0 + srow[p]) * DD + scol);
    }
    CP_COMMIT();

    for (int chunk = 0; chunk < NCH; ++chunk) {
        const int cur = chunk % 3;
        if (chunk + 1 < NCH) {
            const int nxt = (chunk + 1) % 3;
            const int kn = (chunk + 1) * BKC;
            const uint32_t soff = (uint32_t)(nxt * STAGE_F * 4);
            #pragma unroll
            for (int p = 0; p < 4; ++p) {
                cp16(sa[p] + soff, A + io_index<IN_MODE>(m0 + srow[p], kn + scol));
                cp16(sb[p] + soff, W + (n0 + srow[p]) * DD + (kn + scol));
            }
            CP_COMMIT();
            CP_WAIT1();
        } else {
            CP_WAIT0();
        }
        __syncthreads();

        const float* As = smem + cur * STAGE_F;
        const float* Bs = As + 128 * SSTR;

        #pragma unroll
        for (int s = 0; s < 4; ++s) {
            const int ks = s << 3;

            uint32_t afr[4][4];
            #pragma unroll
            for (int mt = 0; mt < 4; ++mt) {
                const int rbse = wm * 64 + mt * 16;
                afr[mt][0] = __float_as_uint(As[(rbse + g) * SSTR + ks + l]);
                afr[mt][1] = __float_as_uint(As[(rbse + g + 8) * SSTR + ks + l]);
                afr[mt][2] = __float_as_uint(As[(rbse + g) * SSTR + ks + l + 4]);
                afr[mt][3] = __float_as_uint(As[(rbse + g + 8) * SSTR + ks + l + 4]);
            }
            uint32_t bfr[4][2];
            #pragma unroll
            for (int nt = 0; nt < 4; ++nt) {
                const int nb = wn * 32 + nt * 8;
                bfr[nt][0] = __float_as_uint(Bs[(nb + g) * SSTR + ks + l]);
                bfr[nt][1] = __float_as_uint(Bs[(nb + g) * SSTR + ks + l + 4]);
            }
            #pragma unroll
            for (int mt = 0; mt < 4; ++mt)
                #pragma unroll
                for (int nt = 0; nt < 4; ++nt)
                    mma_tf32(acc[mt][nt], afr[mt], bfr[nt]);
        }
    }

    #pragma unroll
    for (int nt = 0; nt < 4; ++nt) {
        const int n = n0 + wn * 32 + nt * 8 + 2 * l;
        const float b0 = bias[n];
        const float b1 = bias[n + 1];
        #pragma unroll
        for (int mt = 0; mt < 4; ++mt) {
            const int mlo = m0 + wm * 64 + mt * 16 + g;
            float v00 = acc[mt][nt][0] + b0, v01 = acc[mt][nt][1] + b1;
            float v10 = acc[mt][nt][2] + b0, v11 = acc[mt][nt][3] + b1;
            if (OUT_MODE == 1) {   // QKV outputs: pre-round for the attention kernel
                v00 = to_tf32(v00); v01 = to_tf32(v01);
                v10 = to_tf32(v10); v11 = to_tf32(v11);
            }
            *(float2*)(C + io_index<OUT_MODE>(mlo, n))     = make_float2(v00, v01);
            *(float2*)(C + io_index<OUT_MODE>(mlo + 8, n)) = make_float2(v10, v11);
        }
    }
}

// ---------------- tensor-core tf32 flash attention, cp.async 2-stage ----------------
// CTA: 128 q-rows of one head; k-tiles of 64 keys; warp w owns q-rows [16w,16w+16).
// Operands arrive tf32-pre-rounded (QKV epilogue) -> cp.async direct, no cvt.
// 1/sqrt(64) applied to S post-MMA (exact). P never touches smem: C-frag ->
// A-frag via shfl. 2-stage K/V ring, one barrier per tile.

#define ASTR 68
#define VSTR 72
#define KSTG (64 * ASTR)
#define VSTG (64 * VSTR)
#define ATT_SMEM ((128 * ASTR + 2 * KSTG + 2 * VSTG) * 4)   // 106496 B

__global__ __launch_bounds__(256) void attn_mma_kernel()
{
    extern __shared__ __align__(16) float sm[];
    float* Qs = sm;                       // [128][ASTR]
    float* Kst = Qs + 128 * ASTR;         // 2 x [64][ASTR]
    float* Vst = Kst + 2 * KSTG;          // 2 x [64][VSTR]

    const int bh = blockIdx.y;
    const int qt = blockIdx.x;
    const int q0 = qt << 7;

    const float* __restrict__ Qg = g_q + bh * (LL * HDD);
    const float* __restrict__ Kg = g_k + bh * (LL * HDD);
    const float* __restrict__ Vg = g_v + bh * (LL * HDD);

    const int tid = threadIdx.x;
    const int wid = tid >> 5;
    const int lane = tid & 31;
    const int g = lane >> 2;
    const int l = lane & 3;
    const int wrow = q0 + 16 * wid;

    // K/V tile copy coords: 64 rows x 16 chunks(16B) each; 1024 cp16 per tile
    // per operand, 256 threads x 4. Q: 128 rows x 16 chunks = 2048 = 8/thread.
    const int krow[4] = { (tid + 0) >> 4, (tid + 256) >> 4, (tid + 512) >> 4, (tid + 768) >> 4 };
    const int kc4 = (tid & 15) << 2;   // float offset within row

    // Prologue: Q + K/V tile 0 -> stage 0.
    {
        #pragma unroll
        for (int p = 0; p < 8; ++p) {
            const int r = (tid + 256 * p) >> 4;
            cp16(smem_u32(&Qs[r * ASTR + kc4]), Qg + (q0 + r) * HDD + kc4);   // FIX: + q0
        }
        #pragma unroll
        for (int p = 0; p < 4; ++p) {
            cp16(smem_u32(&Kst[krow[p] * ASTR + kc4]), Kg + krow[p] * HDD + kc4);
            cp16(smem_u32(&Vst[krow[p] * VSTR + kc4]), Vg + krow[p] * HDD + kc4);
        }
        CP_COMMIT();
    }

    float acc_o[8][4] = {};
    float m0 = -1e30f, m1 = -1e30f;
    float l0 = 0.0f, l1 = 0.0f;

    const int nkt = 2 * qt + 2;
    for (int kt = 0; kt < nkt; ++kt) {
        const int k0 = kt << 6;

        CP_WAIT0();        // tile kt (and Q on kt=0) arrived
        __syncthreads();   // cross-thread visibility + stage reuse protection

        // Issue tile kt+1 into the other stage (its prior readers finished at
        // the barrier above); overlaps with this tile's compute.
        if (kt + 1 < nkt) {
            const int kn0 = (kt + 1) << 6;
            float* Kn = Kst + ((kt + 1) & 1) * KSTG;
            float* Vn = Vst + ((kt + 1) & 1) * VSTG;
            #pragma unroll
            for (int p = 0; p < 4; ++p) {
                cp16(smem_u32(&Kn[krow[p] * ASTR + kc4]), Kg + (kn0 + krow[p]) * HDD + kc4);
                cp16(smem_u32(&Vn[krow[p] * VSTR + kc4]), Vg + (kn0 + krow[p]) * HDD + kc4);
            }
            CP_COMMIT();
        }

        if (k0 > wrow + 15) continue;    // warp tile fully above diagonal

        const float* Ks = Kst + (kt & 1) * KSTG;
        const float* Vs = Vst + (kt & 1) * VSTG;

        // ---- S = Q K^T (scale applied after) ----
        float s[8][4] = {};
        #pragma unroll
        for (int st = 0; st < 8; ++st) {
            const int ks = st << 3;
            uint32_t af[4];
            af[0] = __float_as_uint(Qs[(16 * wid + g) * ASTR + ks + l]);
            af[1] = __float_as_uint(Qs[(16 * wid + g + 8) * ASTR + ks + l]);
            af[2] = __float_as_uint(Qs[(16 * wid + g) * ASTR + ks + l + 4]);
            af[3] = __float_as_uint(Qs[(16 * wid + g + 8) * ASTR + ks + l + 4]);
            #pragma unroll
            for (int nt = 0; nt < 8; ++nt) {
                uint32_t bf[2];
                bf[0] = __float_as_uint(Ks[(nt * 8 + g) * ASTR + ks + l]);
                bf[1] = __float_as_uint(Ks[(nt * 8 + g) * ASTR + ks + l + 4]);
                mma_tf32(s[nt], af, bf);
            }
        }

        // ---- scale + causal mask ----
        const int r0 = wrow + g;
        const int r1 = wrow + 8 + g;
        #pragma unroll
        for (int nt = 0; nt < 8; ++nt) {
            s[nt][0] *= 0.125f; s[nt][1] *= 0.125f;
            s[nt][2] *= 0.125f; s[nt][3] *= 0.125f;
        }
        if (k0 + 63 > wrow) {
            #pragma unroll
            for (int nt = 0; nt < 8; ++nt) {
                const int c = k0 + nt * 8 + 2 * l;
                if (c > r0)     s[nt][0] = -1e30f;
                if (c + 1 > r0) s[nt][1] = -1e30f;
                if (c > r1)     s[nt][2] = -1e30f;
                if (c + 1 > r1) s[nt][3] = -1e30f;
            }
        }

        // ---- online softmax (warp-local; lanes sharing g reduce over l) ----
        float mx0 = -1e30f, mx1 = -1e30f;
        #pragma unroll
        for (int nt = 0; nt < 8; ++nt) {
            mx0 = fmaxf(mx0, fmaxf(s[nt][0], s[nt][1]));
            mx1 = fmaxf(mx1, fmaxf(s[nt][2], s[nt][3]));
        }
        #pragma unroll
        for (int off = 2; off >= 1; off >>= 1) {
            mx0 = fmaxf(mx0, __shfl_xor_sync(0xffffffffu, mx0, off));
            mx1 = fmaxf(mx1, __shfl_xor_sync(0xffffffffu, mx1, off));
        }
        const float mn0 = fmaxf(m0, mx0);
        const float mn1 = fmaxf(m1, mx1);
        const float a0 = __expf(m0 - mn0);
        const float a1 = __expf(m1 - mn1);

        float sum0 = 0.0f, sum1 = 0.0f;
        #pragma unroll
        for (int nt = 0; nt < 8; ++nt) {
            s[nt][0] = __expf(s[nt][0] - mn0); sum0 += s[nt][0];
            s[nt][1] = __expf(s[nt][1] - mn0); sum0 += s[nt][1];
            s[nt][2] = __expf(s[nt][2] - mn1); sum1 += s[nt][2];
            s[nt][3] = __expf(s[nt][3] - mn1); sum1 += s[nt][3];
        }
        #pragma unroll
        for (int off = 2; off >= 1; off >>= 1) {
            sum0 += __shfl_xor_sync(0xffffffffu, sum0, off);
            sum1 += __shfl_xor_sync(0xffffffffu, sum1, off);
        }
        l0 = l0 * a0 + sum0;
        l1 = l1 * a1 + sum1;
        m0 = mn0;
        m1 = mn1;

        #pragma unroll
        for (int nt = 0; nt < 8; ++nt) {
            acc_o[nt][0] *= a0; acc_o[nt][1] *= a0;
            acc_o[nt][2] *= a1; acc_o[nt][3] *= a1;
            s[nt][0] = to_tf32(s[nt][0]); s[nt][1] = to_tf32(s[nt][1]);
            s[nt][2] = to_tf32(s[nt][2]); s[nt][3] = to_tf32(s[nt][3]);
        }

        // ---- O += P V : P C-frag -> A-frag via shfl (no smem) ----
        const int src0 = 4 * g + (l >> 1);
        const int src1 = src0 + 2;
        const bool odd = (l & 1);
        #pragma unroll
        for (int st = 0; st < 8; ++st) {
            const float v00 = __shfl_sync(0xffffffffu, s[st][0], src0);
            const float v01 = __shfl_sync(0xffffffffu, s[st][1], src0);
            const float v10 = __shfl_sync(0xffffffffu, s[st][2], src0);
            const float v11 = __shfl_sync(0xffffffffu, s[st][3], src0);
            const float w00 = __shfl_sync(0xffffffffu, s[st][0], src1);
            const float w01 = __shfl_sync(0xffffffffu, s[st][1], src1);
            const float w10 = __shfl_sync(0xffffffffu, s[st][2], src1);
            const float w11 = __shfl_sync(0xffffffffu, s[st][3], src1);
            uint32_t af[4];
            af[0] = __float_as_uint(odd ? v01 : v00);
            af[1] = __float_as_uint(odd ? v11 : v10);
            af[2] = __float_as_uint(odd ? w01 : w00);
            af[3] = __float_as_uint(odd ? w11 : w10);

            const int ks = st << 3;
            #pragma unroll
            for (int nt = 0; nt < 8; ++nt) {
                uint32_t bf[2];
                bf[0] = __float_as_uint(Vs[(ks + l) * VSTR + nt * 8 + g]);
                bf[1] = __float_as_uint(Vs[(ks + l + 4) * VSTR + nt * 8 + g]);
                mma_tf32(acc_o[nt], af, bf);
            }
        }
    }

    // Normalize and write O rows, tf32-rounded (feeds the O-projection GEMM raw).
    float* Og = g_o + bh * (LL * HDD);
    const float inv0 = 1.0f / l0;
    const float inv1 = 1.0f / l1;
    const int r0 = wrow + g;
    const int r1 = wrow + 8 + g;
    #pragma unroll
    for (int nt = 0; nt < 8; ++nt) {
        const int d = nt * 8 + 2 * l;
        *(float2*)&Og[r0 * HDD + d] =
            make_float2(to_tf32(acc_o[nt][0] * inv0), to_tf32(acc_o[nt][1] * inv0));
        *(float2*)&Og[r1 * HDD + d] =
            make_float2(to_tf32(acc_o[nt][2] * inv1), to_tf32(acc_o[nt][3] * inv1));
    }
}

extern "C" void kernel_launch(void* const* d_in, const int* in_sizes, int n_in,
                              void* d_out, int out_size)
{
    (void)in_sizes; (void)n_in; (void)out_size;

    const float* key   = (const float*)d_in[0];
    const float* value = (const float*)d_in[1];
    const float* query = (const float*)d_in[2];
    const float* Wk    = (const float*)d_in[3];
    const float* bk    = (const float*)d_in[4];
    const float* Wq    = (const float*)d_in[5];
    const float* bq    = (const float*)d_in[6];
    const float* Wv    = (const float*)d_in[7];
    const float* bv    = (const float*)d_in[8];
    const float* Wp    = (const float*)d_in[9];
    const float* bp    = (const float*)d_in[10];
    float* out = (float*)d_out;

    float *q_p, *k_p, *v_p, *o_p;
    float *aq_p, *ak_p, *av_p, *wq_p, *wk_p, *wv_p, *wp_p;
    cudaGetSymbolAddress((void**)&q_p, g_q);
    cudaGetSymbolAddress((void**)&k_p, g_k);
    cudaGetSymbolAddress((void**)&v_p, g_v);
    cudaGetSymbolAddress((void**)&o_p, g_o);
    cudaGetSymbolAddress((void**)&aq_p, g_aq);
    cudaGetSymbolAddress((void**)&ak_p, g_ak);
    cudaGetSymbolAddress((void**)&av_p, g_av);
    cudaGetSymbolAddress((void**)&wq_p, g_wq);
    cudaGetSymbolAddress((void**)&wk_p, g_wk);
    cudaGetSymbolAddress((void**)&wv_p, g_wv);
    cudaGetSymbolAddress((void**)&wp_p, g_wp);

    // Prepass: round all GEMM operands to tf32 once.
    tf32_prepass_kernel<<<dim3(512, 1, 7), 256>>>(
        query, aq_p, MM * DD,
        key,   ak_p, MM * DD,
        value, av_p, MM * DD,
        Wq,    wq_p, DD * DD,
        Wk,    wk_p, DD * DD,
        Wv,    wv_p, DD * DD,
        Wp,    wp_p, DD * DD);

    cudaFuncSetAttribute(gemm_mma_kernel<0, 1>, cudaFuncAttributeMaxDynamicSharedMemorySize, GSMEM);
    cudaFuncSetAttribute(gemm_mma_kernel<1, 0>, cudaFuncAttributeMaxDynamicSharedMemorySize, GSMEM);

    // Fused Q/K/V projections -> [B,H,L,HD], outputs tf32-pre-rounded
    gemm_mma_kernel<0, 1><<<dim3(DD / 128, MM / 128, 3), 256, GSMEM>>>(
        aq_p, wq_p, bq, q_p,
        ak_p, wk_p, bk, k_p,
        av_p, wv_p, bv, v_p);

    // Attention (tensor-core tf32 flash, cp.async 2-stage)
    cudaFuncSetAttribute(attn_mma_kernel, cudaFuncAttributeMaxDynamicSharedMemorySize, ATT_SMEM);
    attn_mma_kernel<<<dim3(LL / 128, BB * HH), 256, ATT_SMEM>>>();

    // Output projection: gather [B,H,L,HD] -> [B,L,D]
    gemm_mma_kernel<1, 0><<<dim3(DD / 128, MM / 128, 1), 256, GSMEM>>>(
        o_p, wp_p, bp, out,
        o_p, wp_p, bp, out,
        o_p, wp_p, bp, out);
}